// round 4
// baseline (speedup 1.0000x reference)
#include <cuda_runtime.h>

#define N_POS 65536   // 16*64*64
#define CIN 64
#define COUT 64

// Scratch (allocation-free rule: __device__ globals)
__device__ float g_q[COUT * N_POS];
__device__ float g_k[COUT * N_POS];
__device__ float g_v[COUT * N_POS];

// ---------------------------------------------------------------------------
// Kernel A: q/k/v 1x1 conv.  One thread per voxel, x[0..63] in registers,
// weights staged in smem (float2 for q,k + float for v -> 2 LDS per 3 FFMA).
// ---------------------------------------------------------------------------
__global__ __launch_bounds__(256) void qkv_kernel(
    const float* __restrict__ x,
    const float* __restrict__ wq,
    const float* __restrict__ wk,
    const float* __restrict__ wv)
{
    __shared__ float2 s_wqk[4096];  // 32 KB
    __shared__ float  s_wv[4096];   // 16 KB  (total 48 KB)

    for (int i = threadIdx.x; i < 4096; i += 256) {
        s_wqk[i] = make_float2(wq[i], wk[i]);
        s_wv[i]  = wv[i];
    }
    __syncthreads();

    int pos = blockIdx.x * 256 + threadIdx.x;  // grid covers exactly 65536

    float xv[64];
#pragma unroll
    for (int c = 0; c < 64; c++) xv[c] = x[c * N_POS + pos];

#pragma unroll 2
    for (int o = 0; o < 64; o++) {
        float aq = 0.f, ak = 0.f, av = 0.f;
#pragma unroll
        for (int c = 0; c < 64; c++) {
            float2 w2 = s_wqk[o * 64 + c];
            float  w3 = s_wv[o * 64 + c];
            float  xc = xv[c];
            aq = fmaf(w2.x, xc, aq);
            ak = fmaf(w2.y, xc, ak);
            av = fmaf(w3,   xc, av);
        }
        g_q[o * N_POS + pos] = aq;
        g_k[o * N_POS + pos] = ak;
        g_v[o * N_POS + pos] = av;
    }
}

// ---------------------------------------------------------------------------
// Kernel B: per-channel 27-tap softmax attention over 3x3x3 window (pad=1).
// Block = (channel c, spatial tile 4x8x16).  k/v halo staged in smem; padded
// taps behave as k=0 (bias still added) and v=0, matching the reference.
// ---------------------------------------------------------------------------
#define TD 4
#define TH 8
#define TW 16
#define SD (TD + 2)
#define SH (TH + 2)
#define SW (TW + 2)
#define HALO (SD * SH * SW)   // 6*10*18 = 1080

__global__ __launch_bounds__(512) void attn_kernel(
    const float* __restrict__ rel_d,
    const float* __restrict__ rel_h,
    const float* __restrict__ rel_w,
    float* __restrict__ out)
{
    __shared__ float sk[HALO];
    __shared__ float sv[HALO];
    __shared__ float sb[27];

    const int c    = blockIdx.y;
    const int tile = blockIdx.x;          // 0..127
    const int tw   = tile & 3;            // W/TW = 4
    const int th   = (tile >> 2) & 7;     // H/TH = 8
    const int td   = tile >> 5;           // D/TD = 4
    const int d0 = td * TD, h0 = th * TH, w0 = tw * TW;
    const int tid = threadIdx.x;

    // Per-channel 27-tap bias (rank-1 in kd/kh/kw depending on channel third)
    if (tid < 27) {
        int kd = tid / 9, kh = (tid / 3) % 3, kw = tid % 3;
        float b;
        if (c < 21)      b = rel_d[c * 3 + kd];
        else if (c < 42) b = rel_h[(c - 21) * 3 + kh];
        else             b = rel_w[(c - 42) * 3 + kw];
        sb[tid] = b;
    }

    const float* kc = g_k + c * N_POS;
    const float* vc = g_v + c * N_POS;

    // Cooperative halo load with zero-padding at volume borders
    for (int i = tid; i < HALO; i += 512) {
        int z = i / (SH * SW);
        int r = i - z * (SH * SW);
        int y = r / SW;
        int xw = r - y * SW;
        int gd = d0 - 1 + z, gh = h0 - 1 + y, gw = w0 - 1 + xw;
        float kvv = 0.f, vvv = 0.f;
        if ((unsigned)gd < 16u && (unsigned)gh < 64u && (unsigned)gw < 64u) {
            int gi = (gd << 12) + (gh << 6) + gw;
            kvv = kc[gi];
            vvv = vc[gi];
        }
        sk[i] = kvv;
        sv[i] = vvv;
    }
    __syncthreads();

    const int lw = tid & 15;
    const int lh = (tid >> 4) & 7;
    const int ld = tid >> 7;
    const int gpos = c * N_POS + ((d0 + ld) << 12) + ((h0 + lh) << 6) + (w0 + lw);
    const float q = g_q[gpos];

    const int base = ld * (SH * SW) + lh * SW + lw;

    float s[27];
    float m = -1e30f;
#pragma unroll
    for (int j = 0; j < 27; j++) {
        int kd = j / 9, kh = (j / 3) % 3, kw = j % 3;
        float kv = sk[base + kd * (SH * SW) + kh * SW + kw] + sb[j];
        float sj = q * kv;
        s[j] = sj;
        m = fmaxf(m, sj);
    }

    float sp = 0.f, acc = 0.f;
#pragma unroll
    for (int j = 0; j < 27; j++) {
        int kd = j / 9, kh = (j / 3) % 3, kw = j % 3;
        float p = __expf(s[j] - m);
        sp += p;
        acc = fmaf(p, sv[base + kd * (SH * SW) + kh * SW + kw], acc);
    }

    out[gpos] = __fdividef(acc, sp);
}

// ---------------------------------------------------------------------------
extern "C" void kernel_launch(void* const* d_in, const int* in_sizes, int n_in,
                              void* d_out, int out_size)
{
    const float* x     = (const float*)d_in[0];
    const float* wq    = (const float*)d_in[1];
    const float* wk    = (const float*)d_in[2];
    const float* wv    = (const float*)d_in[3];
    const float* rel_d = (const float*)d_in[4];
    const float* rel_h = (const float*)d_in[5];
    const float* rel_w = (const float*)d_in[6];
    float* out = (float*)d_out;

    qkv_kernel<<<N_POS / 256, 256>>>(x, wq, wk, wv);
    attn_kernel<<<dim3(128, 64), 512>>>(rel_d, rel_h, rel_w, out);
}

// round 6
// speedup vs baseline: 1.4743x; 1.4743x over previous
#include <cuda_runtime.h>

#define N_POS 65536   // 16*64*64
#define CIN 64
#define COUT 64

// Scratch (allocation-free rule: __device__ globals)
__device__ float g_q[COUT * N_POS];
__device__ float g_k[COUT * N_POS];
__device__ float g_v[COUT * N_POS];

typedef unsigned long long u64;

__device__ __forceinline__ u64 ffma2(u64 a, u64 b, u64 c) {
    u64 d;
    asm("fma.rn.f32x2 %0, %1, %2, %3;" : "=l"(d) : "l"(a), "l"(b), "l"(c));
    return d;
}
__device__ __forceinline__ u64 pack2(float lo, float hi) {
    u64 d;
    asm("mov.b64 %0, {%1, %2};" : "=l"(d) : "f"(lo), "f"(hi));
    return d;
}
__device__ __forceinline__ float2 unpack2(u64 v) {
    float2 r;
    asm("mov.b64 {%0, %1}, %2;" : "=f"(r.x), "=f"(r.y) : "l"(v));
    return r;
}
__device__ __forceinline__ float ex2f(float x) {
    float r;
    asm("ex2.approx.ftz.f32 %0, %1;" : "=f"(r) : "f"(x));
    return r;
}

// ---------------------------------------------------------------------------
// Kernel A: q/k/v 1x1 conv with packed f32x2 FFMA.
// One thread per voxel; x packed into 32 f32x2 regs; weights staged in smem
// as bit-packed c-pairs so a broadcast LDS.64 feeds fma.rn.f32x2 directly.
// ---------------------------------------------------------------------------
__global__ __launch_bounds__(256) void qkv_kernel(
    const float* __restrict__ x,
    const float* __restrict__ wq,
    const float* __restrict__ wk,
    const float* __restrict__ wv)
{
    __shared__ u64 s_wq[2048];  // 64 o x 32 c-pairs, 16 KB
    __shared__ u64 s_wk[2048];
    __shared__ u64 s_wv[2048];  // total 48 KB

    const u64* wq2 = (const u64*)wq;  // c-adjacent floats are contiguous
    const u64* wk2 = (const u64*)wk;
    const u64* wv2 = (const u64*)wv;
    for (int i = threadIdx.x; i < 2048; i += 256) {
        s_wq[i] = wq2[i];
        s_wk[i] = wk2[i];
        s_wv[i] = wv2[i];
    }
    __syncthreads();

    const int pos = blockIdx.x * 256 + threadIdx.x;

    u64 xp[32];
#pragma unroll
    for (int c2 = 0; c2 < 32; c2++)
        xp[c2] = pack2(x[(2 * c2) * N_POS + pos], x[(2 * c2 + 1) * N_POS + pos]);

#pragma unroll 2
    for (int o = 0; o < 64; o++) {
        u64 aq = 0ull, ak = 0ull, av = 0ull;
#pragma unroll
        for (int c2 = 0; c2 < 32; c2++) {
            u64 xc = xp[c2];
            aq = ffma2(s_wq[o * 32 + c2], xc, aq);
            ak = ffma2(s_wk[o * 32 + c2], xc, ak);
            av = ffma2(s_wv[o * 32 + c2], xc, av);
        }
        float2 q = unpack2(aq);
        float2 k = unpack2(ak);
        float2 v = unpack2(av);
        g_q[o * N_POS + pos] = q.x + q.y;
        g_k[o * N_POS + pos] = k.x + k.y;
        g_v[o * N_POS + pos] = v.x + v.y;
    }
}

// ---------------------------------------------------------------------------
// Kernel B: per-channel 27-tap softmax attention, 4 outputs per thread along W.
// Block = (channel, 4x8x64 spatial tile), 512 threads.
// Halo in smem with col index = w+1 and row stride 68 so each thread's 6-tap
// span starts 16B-aligned -> LDS.128 + LDS.64 per (kd,kh) row per array.
// Softmax computed WITHOUT max subtraction (scale-invariant; |s|*log2e << 127
// for these magnitudes), log2e folded into q: one EX2 per tap.
// ---------------------------------------------------------------------------
#define TD 4
#define TH 8
#define SD (TD + 2)
#define SH (TH + 2)
#define ROW 68            // 66 used cols (w = -1..64), padded to mult of 4
#define PLANE (SH * ROW)  // 680
#define HALO (SD * PLANE) // 4080

__global__ __launch_bounds__(512) void attn_kernel(
    const float* __restrict__ rel_d,
    const float* __restrict__ rel_h,
    const float* __restrict__ rel_w,
    float* __restrict__ out)
{
    __shared__ __align__(16) float sk[HALO];
    __shared__ __align__(16) float sv[HALO];
    __shared__ float sb[27];

    const int c    = blockIdx.y;
    const int tile = blockIdx.x;       // 0..31
    const int th   = tile & 7;         // H/TH = 8
    const int td   = tile >> 3;        // D/TD = 4
    const int d0 = td * TD, h0 = th * TH;
    const int tid = threadIdx.x;

    if (tid < 27) {
        int kd = tid / 9, kh = (tid / 3) % 3, kw = tid % 3;
        float b;
        if (c < 21)      b = rel_d[c * 3 + kd];
        else if (c < 42) b = rel_h[(c - 21) * 3 + kh];
        else             b = rel_w[(c - 42) * 3 + kw];
        sb[tid] = b;
    }

    const float* kc = g_k + c * N_POS;
    const float* vc = g_v + c * N_POS;

    // Cooperative halo load: smem col i <-> global w = i-1, zero-pad OOB
    for (int i = tid; i < HALO; i += 512) {
        int z   = i / PLANE;
        int r   = i - z * PLANE;
        int y   = r / ROW;
        int col = r - y * ROW;
        int gd = d0 - 1 + z, gh = h0 - 1 + y, gw = col - 1;
        float kvv = 0.f, vvv = 0.f;
        if ((unsigned)gd < 16u && (unsigned)gh < 64u && (unsigned)gw < 64u) {
            int gi = (gd << 12) + (gh << 6) + gw;
            kvv = kc[gi];
            vvv = vc[gi];
        }
        sk[i] = kvv;
        sv[i] = vvv;
    }
    __syncthreads();

    const int lw = tid & 15;          // 16 w-groups of 4 outputs
    const int lh = (tid >> 4) & 7;
    const int ld = tid >> 7;

    const int gbase = c * N_POS + ((d0 + ld) << 12) + ((h0 + lh) << 6) + 4 * lw;
    const float4 qv = *(const float4*)(g_q + gbase);

    const float LOG2E = 1.4426950408889634f;
    float q2[4] = {qv.x * LOG2E, qv.y * LOG2E, qv.z * LOG2E, qv.w * LOG2E};
    float sp[4] = {0.f, 0.f, 0.f, 0.f};
    float acc[4] = {0.f, 0.f, 0.f, 0.f};

#pragma unroll
    for (int kd = 0; kd < 3; kd++) {
#pragma unroll
        for (int kh = 0; kh < 3; kh++) {
            const int roff = (ld + kd) * PLANE + (lh + kh) * ROW + 4 * lw;
            const float4 ka = *(const float4*)&sk[roff];
            const float2 kb = *(const float2*)&sk[roff + 4];
            const float4 va = *(const float4*)&sv[roff];
            const float2 vb = *(const float2*)&sv[roff + 4];
            float kk[6] = {ka.x, ka.y, ka.z, ka.w, kb.x, kb.y};
            float vv[6] = {va.x, va.y, va.z, va.w, vb.x, vb.y};
#pragma unroll
            for (int kw = 0; kw < 3; kw++) {
                const float b = sb[(kd * 3 + kh) * 3 + kw];
#pragma unroll
                for (int t = 0; t < 4; t++) {
                    float p = ex2f(q2[t] * (kk[t + kw] + b));
                    sp[t] += p;
                    acc[t] = fmaf(p, vv[t + kw], acc[t]);
                }
            }
        }
    }

    float4 o4;
    o4.x = __fdividef(acc[0], sp[0]);
    o4.y = __fdividef(acc[1], sp[1]);
    o4.z = __fdividef(acc[2], sp[2]);
    o4.w = __fdividef(acc[3], sp[3]);
    *(float4*)(out + gbase) = o4;
}

// ---------------------------------------------------------------------------
extern "C" void kernel_launch(void* const* d_in, const int* in_sizes, int n_in,
                              void* d_out, int out_size)
{
    const float* x     = (const float*)d_in[0];
    const float* wq    = (const float*)d_in[1];
    const float* wk    = (const float*)d_in[2];
    const float* wv    = (const float*)d_in[3];
    const float* rel_d = (const float*)d_in[4];
    const float* rel_h = (const float*)d_in[5];
    const float* rel_w = (const float*)d_in[6];
    float* out = (float*)d_out;

    qkv_kernel<<<N_POS / 256, 256>>>(x, wq, wk, wv);
    attn_kernel<<<dim3(32, 64), 512>>>(rel_d, rel_h, rel_w, out);
}

// round 8
// speedup vs baseline: 1.7319x; 1.1748x over previous
#include <cuda_runtime.h>
#include <cuda_bf16.h>
#include <cstdint>

#define N_POS 65536   // 16*64*64

// Scratch (allocation-free rule: __device__ globals)
__device__ float g_q[64 * N_POS];
__device__ float g_k[64 * N_POS];
__device__ float g_v[64 * N_POS];

// ---------------------------------------------------------------------------
// Helpers (arch-agnostic PTX only: mma.sync + ldmatrix, sm_80+)
// ---------------------------------------------------------------------------
__device__ __forceinline__ uint32_t smem_u32(const void* p) {
    return (uint32_t)__cvta_generic_to_shared(p);
}

__device__ __forceinline__ void mma_bf16(float* c, const uint32_t* a, uint32_t b0, uint32_t b1) {
    asm volatile(
        "mma.sync.aligned.m16n8k16.row.col.f32.bf16.bf16.f32 "
        "{%0,%1,%2,%3}, {%4,%5,%6,%7}, {%8,%9}, {%0,%1,%2,%3};"
        : "+f"(c[0]), "+f"(c[1]), "+f"(c[2]), "+f"(c[3])
        : "r"(a[0]), "r"(a[1]), "r"(a[2]), "r"(a[3]), "r"(b0), "r"(b1));
}

#define LDSM_X4(r0, r1, r2, r3, addr)                                          \
    asm volatile("ldmatrix.sync.aligned.m8n8.x4.shared.b16 {%0,%1,%2,%3}, [%4];" \
                 : "=r"(r0), "=r"(r1), "=r"(r2), "=r"(r3) : "r"(addr))

__device__ __forceinline__ void bf16split(float x, uint16_t& h, uint16_t& l) {
    __nv_bfloat16 hb = __float2bfloat16(x);
    __nv_bfloat16 lb = __float2bfloat16(x - __bfloat162float(hb));
    h = __bfloat16_as_ushort(hb);
    l = __bfloat16_as_ushort(lb);
}
__device__ __forceinline__ uint32_t pck(uint16_t lo, uint16_t hi) {
    return (uint32_t)lo | ((uint32_t)hi << 16);
}

// ---------------------------------------------------------------------------
// Kernel A: q/k/v 1x1 conv as bf16 HMMA GEMM with 2-term split
// (hi*hi + hi*lo + lo*hi, fp32 accumulate -> ~1e-5 rel err).
// CTA = 128 positions, 384 threads = 12 warps = {q,k,v} x 4 row-groups of 16.
// Warp tile: 16 rows x 128 positions.  B (x tile) staged in smem k-major,
// col stride 144B (conflict-free ldmatrix).  A (weights) loaded straight
// into fragment registers from gmem (tiny, L2-resident).
// ---------------------------------------------------------------------------
#define PTILE 128
#define CSTR 36   // uint32 stride per position column (36*4 = 144 B)

__global__ __launch_bounds__(384, 1) void qkv_mma_kernel(
    const float* __restrict__ x,
    const float* __restrict__ wq,
    const float* __restrict__ wk,
    const float* __restrict__ wv)
{
    __shared__ uint32_t sXhi[PTILE * CSTR];   // 18432 B
    __shared__ uint32_t sXlo[PTILE * CSTR];   // 18432 B

    const int tid  = threadIdx.x;
    const int wid  = tid >> 5;
    const int lane = tid & 31;
    const int pos0 = blockIdx.x * PTILE;

    // ---- stage x tile: pos-major gmem reads (coalesced), k-major smem ----
    for (int i = tid; i < PTILE * 32; i += 384) {
        const int pos = i & (PTILE - 1);
        const int cp  = i >> 7;                  // channel pair 0..31
        const float f0 = x[(2 * cp) * N_POS + pos0 + pos];
        const float f1 = x[(2 * cp + 1) * N_POS + pos0 + pos];
        uint16_t h0, l0, h1, l1;
        bf16split(f0, h0, l0);
        bf16split(f1, h1, l1);
        sXhi[pos * CSTR + cp] = pck(h0, h1);
        sXlo[pos * CSTR + cp] = pck(l0, l1);
    }

    // ---- load A fragments (weights) into registers: 4 k-steps, hi+lo ----
    const int g  = wid >> 2;                 // 0=q, 1=k, 2=v
    const int m0 = (wid & 3) << 4;           // row-group base
    const float* wsel = (g == 0) ? wq : (g == 1) ? wk : wv;

    const int r0 = m0 + (lane >> 2);
    const int c0 = (lane & 3) << 1;

    uint32_t ah[4][4], al[4][4];
#pragma unroll
    for (int s = 0; s < 4; s++) {
        const int kb = s << 4;
#pragma unroll
        for (int f = 0; f < 4; f++) {
            const int rr = r0 + ((f & 1) << 3);      // +8 for frags 1,3
            const int cc = kb + c0 + ((f >> 1) << 3); // +8 for frags 2,3
            const float2 w2 = *(const float2*)&wsel[rr * 64 + cc];
            uint16_t h0, l0, h1, l1;
            bf16split(w2.x, h0, l0);
            bf16split(w2.y, h1, l1);
            ah[s][f] = pck(h0, h1);
            al[s][f] = pck(l0, l1);
        }
    }
    __syncthreads();

    // ---- main: 16 n-frags x (3 split-terms x 4 k-steps) HMMA ----
    float acc[16][4];
#pragma unroll
    for (int n = 0; n < 16; n++)
#pragma unroll
        for (int j = 0; j < 4; j++) acc[n][j] = 0.f;

    const uint32_t bhi_base = smem_u32(sXhi);
    const uint32_t blo_base = smem_u32(sXlo);
    // ldmatrix address: column (8n + lane%8), k-chunk (lane/8)*16B
    const uint32_t aoff = (uint32_t)((lane & 7) * (CSTR * 4) + (lane >> 3) * 16);

#pragma unroll
    for (int n = 0; n < 16; n++) {
        const uint32_t coff = aoff + (uint32_t)(n * 8 * (CSTR * 4));
        uint32_t bh[8], bl[8];
        LDSM_X4(bh[0], bh[1], bh[2], bh[3], bhi_base + coff);
        LDSM_X4(bh[4], bh[5], bh[6], bh[7], bhi_base + coff + 64);
        LDSM_X4(bl[0], bl[1], bl[2], bl[3], blo_base + coff);
        LDSM_X4(bl[4], bl[5], bl[6], bl[7], blo_base + coff + 64);
#pragma unroll
        for (int s = 0; s < 4; s++) {
            mma_bf16(acc[n], ah[s], bh[2 * s], bh[2 * s + 1]);   // hi*hi
            mma_bf16(acc[n], ah[s], bl[2 * s], bl[2 * s + 1]);   // hi*lo
            mma_bf16(acc[n], al[s], bh[2 * s], bh[2 * s + 1]);   // lo*hi
        }
    }

    // ---- epilogue: direct stores (32B-sector coalesced) ----
    float* dst = (g == 0) ? g_q : (g == 1) ? g_k : g_v;
    const int rowA = m0 + (lane >> 2);
    const int colb = pos0 + ((lane & 3) << 1);
#pragma unroll
    for (int n = 0; n < 16; n++) {
        const int cc = colb + 8 * n;
        *(float2*)&dst[rowA * N_POS + cc]       = make_float2(acc[n][0], acc[n][1]);
        *(float2*)&dst[(rowA + 8) * N_POS + cc] = make_float2(acc[n][2], acc[n][3]);
    }
}

// ---------------------------------------------------------------------------
// Kernel B: per-channel 27-tap softmax attention, 4 outputs per thread along W.
// (unchanged — 42.4us, near joint fma/MUFU floor)
// ---------------------------------------------------------------------------
#define TD 4
#define TH 8
#define SD (TD + 2)
#define SH (TH + 2)
#define ROW 68
#define PLANE (SH * ROW)
#define HALO (SD * PLANE)

__device__ __forceinline__ float ex2f(float x) {
    float r;
    asm("ex2.approx.ftz.f32 %0, %1;" : "=f"(r) : "f"(x));
    return r;
}

__global__ __launch_bounds__(512) void attn_kernel(
    const float* __restrict__ rel_d,
    const float* __restrict__ rel_h,
    const float* __restrict__ rel_w,
    float* __restrict__ out)
{
    __shared__ __align__(16) float sk[HALO];
    __shared__ __align__(16) float sv[HALO];
    __shared__ float sb[27];

    const int c    = blockIdx.y;
    const int tile = blockIdx.x;
    const int th   = tile & 7;
    const int td   = tile >> 3;
    const int d0 = td * TD, h0 = th * TH;
    const int tid = threadIdx.x;

    if (tid < 27) {
        int kd = tid / 9, kh = (tid / 3) % 3, kw = tid % 3;
        float b;
        if (c < 21)      b = rel_d[c * 3 + kd];
        else if (c < 42) b = rel_h[(c - 21) * 3 + kh];
        else             b = rel_w[(c - 42) * 3 + kw];
        sb[tid] = b;
    }

    const float* kc = g_k + c * N_POS;
    const float* vc = g_v + c * N_POS;

    for (int i = tid; i < HALO; i += 512) {
        int z   = i / PLANE;
        int r   = i - z * PLANE;
        int y   = r / ROW;
        int col = r - y * ROW;
        int gd = d0 - 1 + z, gh = h0 - 1 + y, gw = col - 1;
        float kvv = 0.f, vvv = 0.f;
        if ((unsigned)gd < 16u && (unsigned)gh < 64u && (unsigned)gw < 64u) {
            int gi = (gd << 12) + (gh << 6) + gw;
            kvv = kc[gi];
            vvv = vc[gi];
        }
        sk[i] = kvv;
        sv[i] = vvv;
    }
    __syncthreads();

    const int lw = tid & 15;
    const int lh = (tid >> 4) & 7;
    const int ld = tid >> 7;

    const int gbase = c * N_POS + ((d0 + ld) << 12) + ((h0 + lh) << 6) + 4 * lw;
    const float4 qv = *(const float4*)(g_q + gbase);

    const float LOG2E = 1.4426950408889634f;
    float q2[4] = {qv.x * LOG2E, qv.y * LOG2E, qv.z * LOG2E, qv.w * LOG2E};
    float sp[4] = {0.f, 0.f, 0.f, 0.f};
    float acc[4] = {0.f, 0.f, 0.f, 0.f};

#pragma unroll
    for (int kd = 0; kd < 3; kd++) {
#pragma unroll
        for (int kh = 0; kh < 3; kh++) {
            const int roff = (ld + kd) * PLANE + (lh + kh) * ROW + 4 * lw;
            const float4 ka = *(const float4*)&sk[roff];
            const float2 kb = *(const float2*)&sk[roff + 4];
            const float4 va = *(const float4*)&sv[roff];
            const float2 vb = *(const float2*)&sv[roff + 4];
            float kk[6] = {ka.x, ka.y, ka.z, ka.w, kb.x, kb.y};
            float vv[6] = {va.x, va.y, va.z, va.w, vb.x, vb.y};
#pragma unroll
            for (int kw = 0; kw < 3; kw++) {
                const float b = sb[(kd * 3 + kh) * 3 + kw];
#pragma unroll
                for (int t = 0; t < 4; t++) {
                    float p = ex2f(q2[t] * (kk[t + kw] + b));
                    sp[t] += p;
                    acc[t] = fmaf(p, vv[t + kw], acc[t]);
                }
            }
        }
    }

    float4 o4;
    o4.x = __fdividef(acc[0], sp[0]);
    o4.y = __fdividef(acc[1], sp[1]);
    o4.z = __fdividef(acc[2], sp[2]);
    o4.w = __fdividef(acc[3], sp[3]);
    *(float4*)(out + gbase) = o4;
}

// ---------------------------------------------------------------------------
extern "C" void kernel_launch(void* const* d_in, const int* in_sizes, int n_in,
                              void* d_out, int out_size)
{
    const float* x     = (const float*)d_in[0];
    const float* wq    = (const float*)d_in[1];
    const float* wk    = (const float*)d_in[2];
    const float* wv    = (const float*)d_in[3];
    const float* rel_d = (const float*)d_in[4];
    const float* rel_h = (const float*)d_in[5];
    const float* rel_w = (const float*)d_in[6];
    float* out = (float*)d_out;

    qkv_mma_kernel<<<N_POS / PTILE, 384>>>(x, wq, wk, wv);
    attn_kernel<<<dim3(32, 64), 512>>>(rel_d, rel_h, rel_w, out);
}